// round 2
// baseline (speedup 1.0000x reference)
#include <cuda_runtime.h>
#include <cuda_bf16.h>
#include <cstdint>

// Problem constants
#define BATCH    2
#define SEQ      2048
#define HID      4096
#define NHEADS   32
#define NKV      8
#define HDIM     128
#define QKV_N    6144          // 32*128 + 8*128 + 8*128
#define MTOK     (BATCH*SEQ)   // 4096 token rows

// Scratch (device globals: allowed; no runtime allocation)
__device__ float g_qkv[(size_t)MTOK * QKV_N];   // [4096][6144]  (~96 MB)
__device__ float g_attn[(size_t)MTOK * HID];    // [4096][4096]  (~64 MB)

// ---------------------------------------------------------------------------
// SGEMM (TN): C[m][n] = sum_k A[m*K+k] * B[n*K+k]
// 128x128 tile, 16 k-slice, 256 threads, 8x8 microtile, gmem->reg prefetch.
// ---------------------------------------------------------------------------
__global__ __launch_bounds__(256) void sgemm_tn(
    const float* __restrict__ A,
    const float* __restrict__ B,
    float* __restrict__ C,
    int M, int N, int K)
{
    __shared__ float As[16][132];
    __shared__ float Bs[16][132];

    const int tid = threadIdx.x;
    const int tx  = tid & 15;   // n-dir
    const int ty  = tid >> 4;   // m-dir
    const int bm  = blockIdx.y * 128;
    const int bn  = blockIdx.x * 128;

    const float* Ag = A + (size_t)bm * K;
    const float* Bg = B + (size_t)bn * K;

    float acc[8][8];
#pragma unroll
    for (int i = 0; i < 8; i++)
#pragma unroll
        for (int j = 0; j < 8; j++) acc[i][j] = 0.0f;

    float4 pa[2], pb[2];
    const int kt_total = K >> 4;

    // initial load
#pragma unroll
    for (int r = 0; r < 2; r++) {
        int lin = tid + 256 * r;
        int row = lin >> 2, q = lin & 3;
        pa[r] = *(const float4*)(Ag + (size_t)row * K + q * 4);
        pb[r] = *(const float4*)(Bg + (size_t)row * K + q * 4);
    }
#pragma unroll
    for (int r = 0; r < 2; r++) {
        int lin = tid + 256 * r;
        int row = lin >> 2, q = lin & 3;
        As[q*4+0][row] = pa[r].x; As[q*4+1][row] = pa[r].y;
        As[q*4+2][row] = pa[r].z; As[q*4+3][row] = pa[r].w;
        Bs[q*4+0][row] = pb[r].x; Bs[q*4+1][row] = pb[r].y;
        Bs[q*4+2][row] = pb[r].z; Bs[q*4+3][row] = pb[r].w;
    }
    __syncthreads();

    for (int kt = 0; kt < kt_total; kt++) {
        if (kt + 1 < kt_total) {
            const int ko = (kt + 1) * 16;
#pragma unroll
            for (int r = 0; r < 2; r++) {
                int lin = tid + 256 * r;
                int row = lin >> 2, q = lin & 3;
                pa[r] = *(const float4*)(Ag + (size_t)row * K + ko + q * 4);
                pb[r] = *(const float4*)(Bg + (size_t)row * K + ko + q * 4);
            }
        }
#pragma unroll
        for (int k = 0; k < 16; k++) {
            float4 a0 = *(const float4*)&As[k][ty * 8];
            float4 a1 = *(const float4*)&As[k][ty * 8 + 4];
            float4 b0 = *(const float4*)&Bs[k][tx * 8];
            float4 b1 = *(const float4*)&Bs[k][tx * 8 + 4];
            float av[8] = {a0.x, a0.y, a0.z, a0.w, a1.x, a1.y, a1.z, a1.w};
            float bv[8] = {b0.x, b0.y, b0.z, b0.w, b1.x, b1.y, b1.z, b1.w};
#pragma unroll
            for (int i = 0; i < 8; i++)
#pragma unroll
                for (int j = 0; j < 8; j++)
                    acc[i][j] += av[i] * bv[j];
        }
        __syncthreads();
        if (kt + 1 < kt_total) {
#pragma unroll
            for (int r = 0; r < 2; r++) {
                int lin = tid + 256 * r;
                int row = lin >> 2, q = lin & 3;
                As[q*4+0][row] = pa[r].x; As[q*4+1][row] = pa[r].y;
                As[q*4+2][row] = pa[r].z; As[q*4+3][row] = pa[r].w;
                Bs[q*4+0][row] = pb[r].x; Bs[q*4+1][row] = pb[r].y;
                Bs[q*4+2][row] = pb[r].z; Bs[q*4+3][row] = pb[r].w;
            }
            __syncthreads();
        }
    }

    float* Cg = C + (size_t)bm * N + bn;
#pragma unroll
    for (int i = 0; i < 8; i++) {
        float4 c0 = make_float4(acc[i][0], acc[i][1], acc[i][2], acc[i][3]);
        float4 c1 = make_float4(acc[i][4], acc[i][5], acc[i][6], acc[i][7]);
        *(float4*)(Cg + (size_t)(ty * 8 + i) * N + tx * 8)     = c0;
        *(float4*)(Cg + (size_t)(ty * 8 + i) * N + tx * 8 + 4) = c1;
    }
}

// ---------------------------------------------------------------------------
// RoPE in-place on q (heads 0..31) and k (heads 32..39) of g_qkv.
// One thread per (token, head, pair-dim d in 0..63).
// ---------------------------------------------------------------------------
__global__ __launch_bounds__(256) void rope_kernel(
    float* __restrict__ qkv, const int* __restrict__ positions)
{
    int idx = blockIdx.x * blockDim.x + threadIdx.x;   // B*S*40*64 threads
    int d    = idx & 63;
    int t    = idx >> 6;
    int head = t % 40;
    int tok  = t / 40;

    float pos = (float)positions[tok];
    int off = (head < 32) ? head * 128 : 4096 + (head - 32) * 128;
    float* p = qkv + (size_t)tok * QKV_N + off;

    // inv_freq = theta^(-d/64) ;  ln(1e6)/64 = 0.21586735246819178
    float freq = pos * expf(-(float)d * 0.21586735246819178f);
    float s, c;
    sincosf(freq, &s, &c);

    float x1 = p[d];
    float x2 = p[d + 64];
    p[d]      = x1 * c - x2 * s;
    p[d + 64] = x2 * c + x1 * s;
}

// ---------------------------------------------------------------------------
// Causal flash attention, GQA (4 q-heads per kv-head).
// Block: one (batch, q-head, 64-row q-tile). 256 threads.
// smem: Qs[64][128], Ks[64][132], Vs[64][128], Ps[64][66], row stats.
// ---------------------------------------------------------------------------
#define FLASH_SMEM_FLOATS (64*128 + 64*132 + 64*128 + 64*66 + 3*64)
#define FLASH_SMEM_BYTES  (FLASH_SMEM_FLOATS * 4)

__global__ __launch_bounds__(256) void flash_kernel(
    const float* __restrict__ qkv, float* __restrict__ attn_out)
{
    extern __shared__ float sm[];
    float* Qs   = sm;                 // [64][128]
    float* Ks   = Qs + 64 * 128;      // [64][132]
    float* Vs   = Ks + 64 * 132;      // [64][128]
    float* Ps   = Vs + 64 * 128;      // [64][66]
    float* mrow = Ps + 64 * 66;       // [64]
    float* lrow = mrow + 64;          // [64]
    float* crow = lrow + 64;          // [64]

    const int tid = threadIdx.x;
    const int tx  = tid & 15;
    const int ty  = tid >> 4;

    const int bid = blockIdx.x;
    const int qt  = bid & 31;          // q tile (S/64 = 32)
    const int h   = (bid >> 5) & 31;   // q head
    const int b   = bid >> 10;         // batch
    const int g   = h >> 2;            // kv head

    const float scale = 0.08838834764831845f;  // 1/sqrt(128)

    const float* qbase = qkv + ((size_t)(b * SEQ) + qt * 64) * QKV_N + h * 128;

    // load Q tile (scaled)
#pragma unroll
    for (int i = 0; i < 8; i++) {
        int lin = tid + 256 * i;       // 2048 float4s
        int row = lin >> 5, c4 = lin & 31;
        float4 v = *(const float4*)(qbase + (size_t)row * QKV_N + c4 * 4);
        v.x *= scale; v.y *= scale; v.z *= scale; v.w *= scale;
        *(float4*)(Qs + row * 128 + c4 * 4) = v;
    }
    if (tid < 64) { mrow[tid] = -1e30f; lrow[tid] = 0.0f; }

    float oacc[4][8];
#pragma unroll
    for (int i = 0; i < 4; i++)
#pragma unroll
        for (int j = 0; j < 8; j++) oacc[i][j] = 0.0f;

    __syncthreads();

    const float* kbase0 = qkv + (size_t)(b * SEQ) * QKV_N + 4096 + g * 128;
    const float* vbase0 = kbase0 + 1024;

    for (int jt = 0; jt <= qt; jt++) {
        const float* kb = kbase0 + (size_t)(jt * 64) * QKV_N;
        const float* vb = vbase0 + (size_t)(jt * 64) * QKV_N;
#pragma unroll
        for (int i = 0; i < 8; i++) {
            int lin = tid + 256 * i;
            int row = lin >> 5, c4 = lin & 31;
            *(float4*)(Ks + row * 132 + c4 * 4) =
                *(const float4*)(kb + (size_t)row * QKV_N + c4 * 4);
            *(float4*)(Vs + row * 128 + c4 * 4) =
                *(const float4*)(vb + (size_t)row * QKV_N + c4 * 4);
        }
        __syncthreads();

        // S = Q K^T  (each thread: 4 q-rows x 4 k-cols)
        float sacc[4][4];
#pragma unroll
        for (int i = 0; i < 4; i++)
#pragma unroll
            for (int j = 0; j < 4; j++) sacc[i][j] = 0.0f;

#pragma unroll 4
        for (int k = 0; k < 128; k += 4) {
            float4 qv[4], kv[4];
#pragma unroll
            for (int i = 0; i < 4; i++)
                qv[i] = *(const float4*)(Qs + (ty + 16 * i) * 128 + k);
#pragma unroll
            for (int j = 0; j < 4; j++)
                kv[j] = *(const float4*)(Ks + (tx + 16 * j) * 132 + k);
#pragma unroll
            for (int i = 0; i < 4; i++)
#pragma unroll
                for (int j = 0; j < 4; j++)
                    sacc[i][j] += qv[i].x * kv[j].x + qv[i].y * kv[j].y
                                + qv[i].z * kv[j].z + qv[i].w * kv[j].w;
        }

        const bool diag = (jt == qt);
#pragma unroll
        for (int i = 0; i < 4; i++) {
            int qr = ty + 16 * i;
#pragma unroll
            for (int j = 0; j < 4; j++) {
                int kc = tx + 16 * j;
                float s = sacc[i][j];
                if (diag && kc > qr) s = -1e30f;
                Ps[qr * 66 + kc] = s;
            }
        }
        __syncthreads();

        // online softmax: 4 threads per row, 16 cols each
        {
            int row = tid >> 2;
            int sub = tid & 3;
            float mx = -1e30f;
#pragma unroll
            for (int t = 0; t < 16; t++)
                mx = fmaxf(mx, Ps[row * 66 + sub * 16 + t]);
            mx = fmaxf(mx, __shfl_xor_sync(0xffffffffu, mx, 1));
            mx = fmaxf(mx, __shfl_xor_sync(0xffffffffu, mx, 2));
            float mold = mrow[row];
            float mnew = fmaxf(mold, mx);
            float sum = 0.0f;
#pragma unroll
            for (int t = 0; t < 16; t++) {
                float p = __expf(Ps[row * 66 + sub * 16 + t] - mnew);
                Ps[row * 66 + sub * 16 + t] = p;
                sum += p;
            }
            sum += __shfl_xor_sync(0xffffffffu, sum, 1);
            sum += __shfl_xor_sync(0xffffffffu, sum, 2);
            if (sub == 0) {
                float corr = __expf(mold - mnew);
                lrow[row] = lrow[row] * corr + sum;
                mrow[row] = mnew;
                crow[row] = corr;
            }
        }
        __syncthreads();

        // O = O*corr + P @ V   (each thread: 4 q-rows x 8 dims)
#pragma unroll
        for (int i = 0; i < 4; i++) {
            float c = crow[ty + 16 * i];
#pragma unroll
            for (int j = 0; j < 8; j++) oacc[i][j] *= c;
        }
#pragma unroll 4
        for (int kc = 0; kc < 64; kc++) {
            float pv[4], vv[8];
#pragma unroll
            for (int i = 0; i < 4; i++) pv[i] = Ps[(ty + 16 * i) * 66 + kc];
#pragma unroll
            for (int j = 0; j < 8; j++) vv[j] = Vs[kc * 128 + tx + 16 * j];
#pragma unroll
            for (int i = 0; i < 4; i++)
#pragma unroll
                for (int j = 0; j < 8; j++)
                    oacc[i][j] += pv[i] * vv[j];
        }
        __syncthreads();
    }

    // normalize + write
    float* obase = attn_out + ((size_t)(b * SEQ) + qt * 64) * HID + h * 128;
#pragma unroll
    for (int i = 0; i < 4; i++) {
        int qr = ty + 16 * i;
        float inv = 1.0f / lrow[qr];
#pragma unroll
        for (int j = 0; j < 8; j++)
            obase[(size_t)qr * HID + tx + 16 * j] = oacc[i][j] * inv;
    }
}

// ---------------------------------------------------------------------------
extern "C" void kernel_launch(void* const* d_in, const int* in_sizes, int n_in,
                              void* d_out, int out_size)
{
    const float* hidden    = (const float*)d_in[0];
    const int*   positions = (const int*)  d_in[1];
    const float* w_qkv     = (const float*)d_in[2];
    const float* w_o       = (const float*)d_in[3];
    float*       out       = (float*)d_out;

    float *qkv, *attn;
    cudaGetSymbolAddress((void**)&qkv,  g_qkv);
    cudaGetSymbolAddress((void**)&attn, g_attn);

    cudaFuncSetAttribute(flash_kernel,
                         cudaFuncAttributeMaxDynamicSharedMemorySize,
                         FLASH_SMEM_BYTES);

    // 1) qkv = hidden @ w_qkv^T : [4096,4096] x [6144,4096]^T
    sgemm_tn<<<dim3(QKV_N / 128, MTOK / 128), 256>>>(hidden, w_qkv, qkv,
                                                     MTOK, QKV_N, HID);
    // 2) RoPE on q and k in-place
    rope_kernel<<<(BATCH * SEQ * 40 * 64) / 256, 256>>>(qkv, positions);
    // 3) causal GQA flash attention -> g_attn
    flash_kernel<<<BATCH * NHEADS * (SEQ / 64), 256, FLASH_SMEM_BYTES>>>(qkv, attn);
    // 4) out = attn @ w_o^T : [4096,4096] x [4096,4096]^T
    sgemm_tn<<<dim3(HID / 128, MTOK / 128), 256>>>(attn, w_o, out,
                                                   MTOK, HID, HID);
}

// round 6
// speedup vs baseline: 1.5303x; 1.5303x over previous
#include <cuda_runtime.h>
#include <cuda_bf16.h>
#include <cstdint>

// Problem constants
#define BATCH    2
#define SEQ      2048
#define HID      4096
#define NHEADS   32
#define NKV      8
#define HDIM     128
#define QKV_N    6144          // 32*128 + 8*128 + 8*128
#define MTOK     (BATCH*SEQ)   // 4096 token rows

// ---------------------------------------------------------------------------
// Scratch (device globals: allowed; no runtime allocation)
// ---------------------------------------------------------------------------
__device__ float g_qkv[(size_t)MTOK * QKV_N];    // fp32 qkv after proj (+rope)

__device__ __nv_bfloat16 g_hid_hi[(size_t)MTOK * HID];
__device__ __nv_bfloat16 g_hid_lo[(size_t)MTOK * HID];
__device__ __nv_bfloat16 g_wqkv_hi[(size_t)QKV_N * HID];
__device__ __nv_bfloat16 g_wqkv_lo[(size_t)QKV_N * HID];
__device__ __nv_bfloat16 g_attn_hi[(size_t)MTOK * HID];
__device__ __nv_bfloat16 g_attn_lo[(size_t)MTOK * HID];
__device__ __nv_bfloat16 g_wo_hi[(size_t)HID * HID];
__device__ __nv_bfloat16 g_wo_lo[(size_t)HID * HID];

// ---------------------------------------------------------------------------
// mma.sync + ldmatrix helpers (family-agnostic: valid on .target sm_100)
// ---------------------------------------------------------------------------
__device__ __forceinline__ uint32_t smem_u32(const void* p) {
    uint32_t a;
    asm("{ .reg .u64 t; cvta.to.shared.u64 t, %1; cvt.u32.u64 %0, t; }"
        : "=r"(a) : "l"(p));
    return a;
}

__device__ __forceinline__ void ldsm4(uint32_t* r, uint32_t addr) {
    asm volatile("ldmatrix.sync.aligned.m8n8.x4.shared.b16 {%0,%1,%2,%3}, [%4];"
        : "=r"(r[0]), "=r"(r[1]), "=r"(r[2]), "=r"(r[3]) : "r"(addr));
}

__device__ __forceinline__ void mma_bf16(float* d, const uint32_t* a, const uint32_t* b) {
    asm volatile(
        "mma.sync.aligned.m16n8k16.row.col.f32.bf16.bf16.f32 "
        "{%0,%1,%2,%3}, {%4,%5,%6,%7}, {%8,%9}, {%0,%1,%2,%3};"
        : "+f"(d[0]), "+f"(d[1]), "+f"(d[2]), "+f"(d[3])
        : "r"(a[0]), "r"(a[1]), "r"(a[2]), "r"(a[3]), "r"(b[0]), "r"(b[1]));
}

// ---------------------------------------------------------------------------
// fp32 -> bf16 (hi, lo) splitter:  x ~= hi + lo
// ---------------------------------------------------------------------------
__global__ __launch_bounds__(256) void split_bf16_kernel(
    const float* __restrict__ x,
    __nv_bfloat16* __restrict__ hi,
    __nv_bfloat16* __restrict__ lo,
    size_t n)
{
    size_t i = ((size_t)blockIdx.x * blockDim.x + threadIdx.x) * 4;
    if (i >= n) return;
    float4 v = *(const float4*)(x + i);
    float vs[4] = {v.x, v.y, v.z, v.w};
    __nv_bfloat16 h[4], l[4];
#pragma unroll
    for (int k = 0; k < 4; k++) {
        h[k] = __float2bfloat16(vs[k]);
        l[k] = __float2bfloat16(vs[k] - __bfloat162float(h[k]));
    }
    *(__nv_bfloat162*)(hi + i)     = __nv_bfloat162(h[0], h[1]);
    *(__nv_bfloat162*)(hi + i + 2) = __nv_bfloat162(h[2], h[3]);
    *(__nv_bfloat162*)(lo + i)     = __nv_bfloat162(l[0], l[1]);
    *(__nv_bfloat162*)(lo + i + 2) = __nv_bfloat162(l[2], l[3]);
}

// ---------------------------------------------------------------------------
// Tensor-core GEMM (TN): C[m][n] = sum_k A[m][k]*B[n][k], A/B as bf16 hi/lo.
// mma.sync.m16n8k16, 3 products: Ahi*Bhi + Ahi*Blo + Alo*Bhi, fp32 acc.
// CTA: 128x128 tile, 256 threads (8 warps, 2x4), warp tile 64x32, K-chunk 64.
// SMEM: 4 tiles of [128][64] bf16 (Ahi, Alo, Bhi, Blo), XOR-swizzled rows.
// ---------------------------------------------------------------------------
#define MMAG_SMEM_BYTES (4 * 128 * 64 * 2)   // 64 KB

// gmem -> smem tile loader: 128 rows x 64 bf16 (128B rows), unit = 16B,
// phys_unit = u ^ (r & 7)  (conflict-free for stores and ldmatrix reads)
__device__ __forceinline__ void load_tile64(
    char* sbase, const __nv_bfloat16* __restrict__ g, int ldk, int tid)
{
#pragma unroll
    for (int i = 0; i < 4; i++) {
        int lin = tid + 256 * i;        // 0..1023
        int r = lin >> 3;               // row 0..127
        int u = lin & 7;                // 16B unit 0..7
        uint4 v = *(const uint4*)(g + (size_t)r * ldk + u * 8);
        int phys = u ^ (r & 7);
        *(uint4*)(sbase + r * 128 + phys * 16) = v;
    }
}

__global__ __launch_bounds__(256) void mma_gemm_split(
    const __nv_bfloat16* __restrict__ Ahi, const __nv_bfloat16* __restrict__ Alo,
    const __nv_bfloat16* __restrict__ Bhi, const __nv_bfloat16* __restrict__ Blo,
    float* __restrict__ C, int M, int N, int K)
{
    extern __shared__ char smem[];
    char* sAhi = smem;
    char* sAlo = smem + 128 * 128;          // 128 rows * 128B
    char* sBhi = smem + 2 * 128 * 128;
    char* sBlo = smem + 3 * 128 * 128;

    const int tid  = threadIdx.x;
    const int wid  = tid >> 5;
    const int lane = tid & 31;
    const int warp_m = wid >> 2;            // 0..1  -> 64-row slice
    const int warp_n = wid & 3;             // 0..3  -> 32-col slice

    const int bm = blockIdx.y * 128;
    const int bn = blockIdx.x * 128;

    // ldmatrix per-thread address components
    const int grp = lane >> 3;              // address group 0..3
    const int tt  = lane & 7;
    // A groups: g0: rows m+0..7 @u0 ; g1: rows m+8..15 @u0 ; g2: rows m+0..7 @u0+1 ; g3: rows m+8..15 @u0+1
    const int rowA = tt + (grp & 1) * 8;    // within 16-row tile
    const int duA  = grp >> 1;              // unit offset 0/1
    // B groups: g0: rows n+0..7 @u0 ; g1: rows n+0..7 @u0+1 ; g2: rows n+8..15 @u0 ; g3: rows n+8..15 @u0+1
    const int rowB = tt + (grp >> 1) * 8;
    const int duB  = grp & 1;

    const uint32_t sAhi_u = smem_u32(sAhi);
    const uint32_t sAlo_u = smem_u32(sAlo);
    const uint32_t sBhi_u = smem_u32(sBhi);
    const uint32_t sBlo_u = smem_u32(sBlo);

    float acc[4][4][4];                      // [mt][nt][reg]
#pragma unroll
    for (int i = 0; i < 4; i++)
#pragma unroll
        for (int j = 0; j < 4; j++)
#pragma unroll
            for (int r = 0; r < 4; r++) acc[i][j][r] = 0.0f;

    const __nv_bfloat16* gAhi = Ahi + (size_t)bm * K;
    const __nv_bfloat16* gAlo = Alo + (size_t)bm * K;
    const __nv_bfloat16* gBhi = Bhi + (size_t)bn * K;
    const __nv_bfloat16* gBlo = Blo + (size_t)bn * K;

    const int nchunks = K >> 6;
    for (int kc = 0; kc < nchunks; kc++) {
        const int ko = kc * 64;
        load_tile64(sAhi, gAhi + ko, K, tid);
        load_tile64(sAlo, gAlo + ko, K, tid);
        load_tile64(sBhi, gBhi + ko, K, tid);
        load_tile64(sBlo, gBlo + ko, K, tid);
        __syncthreads();

#pragma unroll
        for (int ks = 0; ks < 4; ks++) {
            const int u0 = ks * 2;

            uint32_t aH[4][4], aL[4][4];
#pragma unroll
            for (int mt = 0; mt < 4; mt++) {
                int row = warp_m * 64 + mt * 16 + rowA;
                int phys = (u0 + duA) ^ (row & 7);
                uint32_t off = row * 128 + phys * 16;
                ldsm4(aH[mt], sAhi_u + off);
                ldsm4(aL[mt], sAlo_u + off);
            }

            uint32_t bH[4][2], bL[4][2];
#pragma unroll
            for (int p = 0; p < 2; p++) {    // n-pair: tiles 2p, 2p+1
                int row = warp_n * 32 + p * 16 + rowB;
                int phys = (u0 + duB) ^ (row & 7);
                uint32_t off = row * 128 + phys * 16;
                uint32_t rh[4], rl[4];
                ldsm4(rh, sBhi_u + off);
                ldsm4(rl, sBlo_u + off);
                bH[2*p][0] = rh[0]; bH[2*p][1] = rh[1];
                bH[2*p+1][0] = rh[2]; bH[2*p+1][1] = rh[3];
                bL[2*p][0] = rl[0]; bL[2*p][1] = rl[1];
                bL[2*p+1][0] = rl[2]; bL[2*p+1][1] = rl[3];
            }

#pragma unroll
            for (int mt = 0; mt < 4; mt++)
#pragma unroll
                for (int nt = 0; nt < 4; nt++) {
                    mma_bf16(acc[mt][nt], aH[mt], bH[nt]);
                    mma_bf16(acc[mt][nt], aH[mt], bL[nt]);
                    mma_bf16(acc[mt][nt], aL[mt], bH[nt]);
                }
        }
        __syncthreads();
    }

    // Epilogue: d0,d1 -> (row, col..col+1); d2,d3 -> (row+8, col..col+1)
#pragma unroll
    for (int mt = 0; mt < 4; mt++) {
        int row = bm + warp_m * 64 + mt * 16 + (lane >> 2);
#pragma unroll
        for (int nt = 0; nt < 4; nt++) {
            int col = bn + warp_n * 32 + nt * 8 + (lane & 3) * 2;
            *(float2*)(C + (size_t)row * N + col) =
                make_float2(acc[mt][nt][0], acc[mt][nt][1]);
            *(float2*)(C + (size_t)(row + 8) * N + col) =
                make_float2(acc[mt][nt][2], acc[mt][nt][3]);
        }
    }
}

// ---------------------------------------------------------------------------
// RoPE in-place on q (heads 0..31) and k (heads 32..39) of g_qkv.
// ---------------------------------------------------------------------------
__global__ __launch_bounds__(256) void rope_kernel(
    float* __restrict__ qkv, const int* __restrict__ positions)
{
    int idx = blockIdx.x * blockDim.x + threadIdx.x;
    int d    = idx & 63;
    int t    = idx >> 6;
    int head = t % 40;
    int tok  = t / 40;

    float pos = (float)positions[tok];
    int off = (head < 32) ? head * 128 : 4096 + (head - 32) * 128;
    float* p = qkv + (size_t)tok * QKV_N + off;

    float freq = pos * expf(-(float)d * 0.21586735246819178f);
    float s, c;
    sincosf(freq, &s, &c);

    float x1 = p[d];
    float x2 = p[d + 64];
    p[d]      = x1 * c - x2 * s;
    p[d + 64] = x2 * c + x1 * s;
}

// ---------------------------------------------------------------------------
// Causal flash attention, GQA (4 q-heads per kv-head) — fp32 compute.
// Writes output directly as bf16 (hi, lo) pairs for the O-projection MMA.
// ---------------------------------------------------------------------------
#define FLASH_SMEM_FLOATS (64*128 + 64*132 + 64*128 + 64*66 + 3*64)
#define FLASH_SMEM_BYTES  (FLASH_SMEM_FLOATS * 4)

__global__ __launch_bounds__(256) void flash_kernel(
    const float* __restrict__ qkv,
    __nv_bfloat16* __restrict__ out_hi,
    __nv_bfloat16* __restrict__ out_lo)
{
    extern __shared__ float sm[];
    float* Qs   = sm;
    float* Ks   = Qs + 64 * 128;
    float* Vs   = Ks + 64 * 132;
    float* Ps   = Vs + 64 * 128;
    float* mrow = Ps + 64 * 66;
    float* lrow = mrow + 64;
    float* crow = lrow + 64;

    const int tid = threadIdx.x;
    const int tx  = tid & 15;
    const int ty  = tid >> 4;

    const int bid = blockIdx.x;
    const int qt  = bid & 31;
    const int h   = (bid >> 5) & 31;
    const int b   = bid >> 10;
    const int g   = h >> 2;

    const float scale = 0.08838834764831845f;

    const float* qbase = qkv + ((size_t)(b * SEQ) + qt * 64) * QKV_N + h * 128;

#pragma unroll
    for (int i = 0; i < 8; i++) {
        int lin = tid + 256 * i;
        int row = lin >> 5, c4 = lin & 31;
        float4 v = *(const float4*)(qbase + (size_t)row * QKV_N + c4 * 4);
        v.x *= scale; v.y *= scale; v.z *= scale; v.w *= scale;
        *(float4*)(Qs + row * 128 + c4 * 4) = v;
    }
    if (tid < 64) { mrow[tid] = -1e30f; lrow[tid] = 0.0f; }

    float oacc[4][8];
#pragma unroll
    for (int i = 0; i < 4; i++)
#pragma unroll
        for (int j = 0; j < 8; j++) oacc[i][j] = 0.0f;

    __syncthreads();

    const float* kbase0 = qkv + (size_t)(b * SEQ) * QKV_N + 4096 + g * 128;
    const float* vbase0 = kbase0 + 1024;

    for (int jt = 0; jt <= qt; jt++) {
        const float* kb = kbase0 + (size_t)(jt * 64) * QKV_N;
        const float* vb = vbase0 + (size_t)(jt * 64) * QKV_N;
#pragma unroll
        for (int i = 0; i < 8; i++) {
            int lin = tid + 256 * i;
            int row = lin >> 5, c4 = lin & 31;
            *(float4*)(Ks + row * 132 + c4 * 4) =
                *(const float4*)(kb + (size_t)row * QKV_N + c4 * 4);
            *(float4*)(Vs + row * 128 + c4 * 4) =
                *(const float4*)(vb + (size_t)row * QKV_N + c4 * 4);
        }
        __syncthreads();

        float sacc[4][4];
#pragma unroll
        for (int i = 0; i < 4; i++)
#pragma unroll
            for (int j = 0; j < 4; j++) sacc[i][j] = 0.0f;

#pragma unroll 4
        for (int k = 0; k < 128; k += 4) {
            float4 qv[4], kv[4];
#pragma unroll
            for (int i = 0; i < 4; i++)
                qv[i] = *(const float4*)(Qs + (ty + 16 * i) * 128 + k);
#pragma unroll
            for (int j = 0; j < 4; j++)
                kv[j] = *(const float4*)(Ks + (tx + 16 * j) * 132 + k);
#pragma unroll
            for (int i = 0; i < 4; i++)
#pragma unroll
                for (int j = 0; j < 4; j++)
                    sacc[i][j] += qv[i].x * kv[j].x + qv[i].y * kv[j].y
                                + qv[i].z * kv[j].z + qv[i].w * kv[j].w;
        }

        const bool diag = (jt == qt);
#pragma unroll
        for (int i = 0; i < 4; i++) {
            int qr = ty + 16 * i;
#pragma unroll
            for (int j = 0; j < 4; j++) {
                int kc = tx + 16 * j;
                float s = sacc[i][j];
                if (diag && kc > qr) s = -1e30f;
                Ps[qr * 66 + kc] = s;
            }
        }
        __syncthreads();

        {
            int row = tid >> 2;
            int sub = tid & 3;
            float mx = -1e30f;
#pragma unroll
            for (int t = 0; t < 16; t++)
                mx = fmaxf(mx, Ps[row * 66 + sub * 16 + t]);
            mx = fmaxf(mx, __shfl_xor_sync(0xffffffffu, mx, 1));
            mx = fmaxf(mx, __shfl_xor_sync(0xffffffffu, mx, 2));
            float mold = mrow[row];
            float mnew = fmaxf(mold, mx);
            float sum = 0.0f;
#pragma unroll
            for (int t = 0; t < 16; t++) {
                float p = __expf(Ps[row * 66 + sub * 16 + t] - mnew);
                Ps[row * 66 + sub * 16 + t] = p;
                sum += p;
            }
            sum += __shfl_xor_sync(0xffffffffu, sum, 1);
            sum += __shfl_xor_sync(0xffffffffu, sum, 2);
            if (sub == 0) {
                float corr = __expf(mold - mnew);
                lrow[row] = lrow[row] * corr + sum;
                mrow[row] = mnew;
                crow[row] = corr;
            }
        }
        __syncthreads();

#pragma unroll
        for (int i = 0; i < 4; i++) {
            float c = crow[ty + 16 * i];
#pragma unroll
            for (int j = 0; j < 8; j++) oacc[i][j] *= c;
        }
#pragma unroll 4
        for (int kc = 0; kc < 64; kc++) {
            float pv[4], vv[8];
#pragma unroll
            for (int i = 0; i < 4; i++) pv[i] = Ps[(ty + 16 * i) * 66 + kc];
#pragma unroll
            for (int j = 0; j < 8; j++) vv[j] = Vs[kc * 128 + tx + 16 * j];
#pragma unroll
            for (int i = 0; i < 4; i++)
#pragma unroll
                for (int j = 0; j < 8; j++)
                    oacc[i][j] += pv[i] * vv[j];
        }
        __syncthreads();
    }

    // normalize + write directly as bf16 hi/lo
    size_t obase = ((size_t)(b * SEQ) + qt * 64) * HID + h * 128;
#pragma unroll
    for (int i = 0; i < 4; i++) {
        int qr = ty + 16 * i;
        float inv = 1.0f / lrow[qr];
#pragma unroll
        for (int j = 0; j < 8; j++) {
            float v = oacc[i][j] * inv;
            __nv_bfloat16 hv = __float2bfloat16(v);
            __nv_bfloat16 lv = __float2bfloat16(v - __bfloat162float(hv));
            size_t idx = obase + (size_t)qr * HID + tx + 16 * j;
            out_hi[idx] = hv;
            out_lo[idx] = lv;
        }
    }
}

// ---------------------------------------------------------------------------
extern "C" void kernel_launch(void* const* d_in, const int* in_sizes, int n_in,
                              void* d_out, int out_size)
{
    const float* hidden    = (const float*)d_in[0];
    const int*   positions = (const int*)  d_in[1];
    const float* w_qkv     = (const float*)d_in[2];
    const float* w_o       = (const float*)d_in[3];
    float*       out       = (float*)d_out;

    float* qkv;
    cudaGetSymbolAddress((void**)&qkv, g_qkv);
    __nv_bfloat16 *hid_hi, *hid_lo, *wqkv_hi, *wqkv_lo;
    __nv_bfloat16 *attn_hi, *attn_lo, *wo_hi, *wo_lo;
    cudaGetSymbolAddress((void**)&hid_hi,  g_hid_hi);
    cudaGetSymbolAddress((void**)&hid_lo,  g_hid_lo);
    cudaGetSymbolAddress((void**)&wqkv_hi, g_wqkv_hi);
    cudaGetSymbolAddress((void**)&wqkv_lo, g_wqkv_lo);
    cudaGetSymbolAddress((void**)&attn_hi, g_attn_hi);
    cudaGetSymbolAddress((void**)&attn_lo, g_attn_lo);
    cudaGetSymbolAddress((void**)&wo_hi,   g_wo_hi);
    cudaGetSymbolAddress((void**)&wo_lo,   g_wo_lo);

    cudaFuncSetAttribute(flash_kernel,
                         cudaFuncAttributeMaxDynamicSharedMemorySize,
                         FLASH_SMEM_BYTES);
    cudaFuncSetAttribute(mma_gemm_split,
                         cudaFuncAttributeMaxDynamicSharedMemorySize,
                         MMAG_SMEM_BYTES);

    // 0) split inputs to bf16 hi/lo
    {
        size_t n_hid  = (size_t)MTOK * HID;
        size_t n_wqkv = (size_t)QKV_N * HID;
        size_t n_wo   = (size_t)HID * HID;
        split_bf16_kernel<<<(unsigned)(n_hid  / 1024), 256>>>(hidden, hid_hi,  hid_lo,  n_hid);
        split_bf16_kernel<<<(unsigned)(n_wqkv / 1024), 256>>>(w_qkv,  wqkv_hi, wqkv_lo, n_wqkv);
        split_bf16_kernel<<<(unsigned)(n_wo   / 1024), 256>>>(w_o,    wo_hi,   wo_lo,   n_wo);
    }

    // 1) qkv = hidden @ w_qkv^T  (mma.sync, split bf16)
    mma_gemm_split<<<dim3(QKV_N / 128, MTOK / 128), 256, MMAG_SMEM_BYTES>>>(
        hid_hi, hid_lo, wqkv_hi, wqkv_lo, qkv, MTOK, QKV_N, HID);

    // 2) RoPE on q and k in-place
    rope_kernel<<<(BATCH * SEQ * 40 * 64) / 256, 256>>>(qkv, positions);

    // 3) causal GQA flash attention -> bf16 hi/lo directly
    flash_kernel<<<BATCH * NHEADS * (SEQ / 64), 256, FLASH_SMEM_BYTES>>>(
        qkv, attn_hi, attn_lo);

    // 4) out = attn @ w_o^T (mma.sync, split bf16)
    mma_gemm_split<<<dim3(HID / 128, MTOK / 128), 256, MMAG_SMEM_BYTES>>>(
        attn_hi, attn_lo, wo_hi, wo_lo, out, MTOK, HID, HID);
}

// round 7
// speedup vs baseline: 3.1943x; 2.0873x over previous
#include <cuda_runtime.h>
#include <cuda_bf16.h>
#include <cstdint>

// Problem constants
#define BATCH    2
#define SEQ      2048
#define HID      4096
#define NHEADS   32
#define NKV      8
#define HDIM     128
#define QKV_N    6144          // 32*128 + 8*128 + 8*128
#define MTOK     (BATCH*SEQ)   // 4096 token rows

// ---------------------------------------------------------------------------
// Scratch (device globals: allowed; no runtime allocation)
// ---------------------------------------------------------------------------
__device__ float g_qkv[(size_t)MTOK * QKV_N];    // fp32 qkv after projection

__device__ __nv_bfloat16 g_hid_hi[(size_t)MTOK * HID];
__device__ __nv_bfloat16 g_hid_lo[(size_t)MTOK * HID];
__device__ __nv_bfloat16 g_wqkv_hi[(size_t)QKV_N * HID];
__device__ __nv_bfloat16 g_wqkv_lo[(size_t)QKV_N * HID];
__device__ __nv_bfloat16 g_attn_hi[(size_t)MTOK * HID];
__device__ __nv_bfloat16 g_attn_lo[(size_t)MTOK * HID];
__device__ __nv_bfloat16 g_wo_hi[(size_t)HID * HID];
__device__ __nv_bfloat16 g_wo_lo[(size_t)HID * HID];

// rope'd q/k and v, split bf16 hi/lo
__device__ __nv_bfloat16 g_q_hi[(size_t)MTOK * NHEADS * HDIM];
__device__ __nv_bfloat16 g_q_lo[(size_t)MTOK * NHEADS * HDIM];
__device__ __nv_bfloat16 g_k_hi[(size_t)MTOK * NKV * HDIM];
__device__ __nv_bfloat16 g_k_lo[(size_t)MTOK * NKV * HDIM];
__device__ __nv_bfloat16 g_v_hi[(size_t)MTOK * NKV * HDIM];
__device__ __nv_bfloat16 g_v_lo[(size_t)MTOK * NKV * HDIM];

// ---------------------------------------------------------------------------
// mma.sync + ldmatrix + cp.async helpers (family-agnostic on .target sm_100)
// ---------------------------------------------------------------------------
__device__ __forceinline__ uint32_t smem_u32(const void* p) {
    uint32_t a;
    asm("{ .reg .u64 t; cvta.to.shared.u64 t, %1; cvt.u32.u64 %0, t; }"
        : "=r"(a) : "l"(p));
    return a;
}
__device__ __forceinline__ void ldsm4(uint32_t* r, uint32_t addr) {
    asm volatile("ldmatrix.sync.aligned.m8n8.x4.shared.b16 {%0,%1,%2,%3}, [%4];"
        : "=r"(r[0]), "=r"(r[1]), "=r"(r[2]), "=r"(r[3]) : "r"(addr));
}
__device__ __forceinline__ void ldsm4t(uint32_t* r, uint32_t addr) {
    asm volatile("ldmatrix.sync.aligned.m8n8.x4.trans.shared.b16 {%0,%1,%2,%3}, [%4];"
        : "=r"(r[0]), "=r"(r[1]), "=r"(r[2]), "=r"(r[3]) : "r"(addr));
}
__device__ __forceinline__ void mma_bf16(float* d, const uint32_t* a, const uint32_t* b) {
    asm volatile(
        "mma.sync.aligned.m16n8k16.row.col.f32.bf16.bf16.f32 "
        "{%0,%1,%2,%3}, {%4,%5,%6,%7}, {%8,%9}, {%0,%1,%2,%3};"
        : "+f"(d[0]), "+f"(d[1]), "+f"(d[2]), "+f"(d[3])
        : "r"(a[0]), "r"(a[1]), "r"(a[2]), "r"(a[3]), "r"(b[0]), "r"(b[1]));
}
__device__ __forceinline__ void cp_async16(uint32_t s, const void* g) {
    asm volatile("cp.async.cg.shared.global [%0], [%1], 16;" :: "r"(s), "l"(g));
}
#define CP_COMMIT() asm volatile("cp.async.commit_group;" ::: "memory")

__device__ __forceinline__ uint32_t pack_bf16(float x, float y) {
    __nv_bfloat162 t = __floats2bfloat162_rn(x, y);
    return *(uint32_t*)&t;
}

// ---------------------------------------------------------------------------
// fp32 -> bf16 (hi, lo) splitter
// ---------------------------------------------------------------------------
__global__ __launch_bounds__(256) void split_bf16_kernel(
    const float* __restrict__ x,
    __nv_bfloat16* __restrict__ hi,
    __nv_bfloat16* __restrict__ lo,
    size_t n)
{
    size_t i = ((size_t)blockIdx.x * blockDim.x + threadIdx.x) * 4;
    if (i >= n) return;
    float4 v = *(const float4*)(x + i);
    float vs[4] = {v.x, v.y, v.z, v.w};
    __nv_bfloat16 h[4], l[4];
#pragma unroll
    for (int k = 0; k < 4; k++) {
        h[k] = __float2bfloat16(vs[k]);
        l[k] = __float2bfloat16(vs[k] - __bfloat162float(h[k]));
    }
    *(__nv_bfloat162*)(hi + i)     = __nv_bfloat162(h[0], h[1]);
    *(__nv_bfloat162*)(hi + i + 2) = __nv_bfloat162(h[2], h[3]);
    *(__nv_bfloat162*)(lo + i)     = __nv_bfloat162(l[0], l[1]);
    *(__nv_bfloat162*)(lo + i + 2) = __nv_bfloat162(l[2], l[3]);
}

// ---------------------------------------------------------------------------
// Tensor-core GEMM (TN), cp.async double-buffered.
// C[m][n] = sum_k A[m][k]*B[n][k]; split bf16: Ahi*Bhi + Ahi*Blo + Alo*Bhi.
// CTA tile 128x64, K-chunk 64. 256 threads = 8 warps (4m x 2n), warp 32x32.
// Stage (48KB): Ahi[128][64] Alo Bhi[64][64] Blo; 2 stages = 96KB -> 2 CTA/SM.
// ---------------------------------------------------------------------------
#define GS_STAGE   49152
#define GEMM_SMEM_BYTES (2 * GS_STAGE)

__device__ __forceinline__ void gemm_stage_load(
    uint32_t stu,
    const __nv_bfloat16* __restrict__ gAhi, const __nv_bfloat16* __restrict__ gAlo,
    const __nv_bfloat16* __restrict__ gBhi, const __nv_bfloat16* __restrict__ gBlo,
    int K, int ko, int tid)
{
#pragma unroll
    for (int i = 0; i < 8; i++) {           // A tiles: 2048 x 16B
        int lin = tid + 256 * i;
        int tile = lin >> 10, rem = lin & 1023;
        int r = rem >> 3, u = rem & 7;
        const __nv_bfloat16* g = (tile ? gAlo : gAhi) + (size_t)r * K + ko + u * 8;
        cp_async16(stu + tile * 16384 + r * 128 + ((u ^ (r & 7)) << 4), g);
    }
#pragma unroll
    for (int i = 0; i < 4; i++) {           // B tiles: 1024 x 16B
        int lin = tid + 256 * i;
        int tile = lin >> 9, rem = lin & 511;
        int r = rem >> 3, u = rem & 7;
        const __nv_bfloat16* g = (tile ? gBlo : gBhi) + (size_t)r * K + ko + u * 8;
        cp_async16(stu + 32768 + tile * 8192 + r * 128 + ((u ^ (r & 7)) << 4), g);
    }
    CP_COMMIT();
}

__global__ __launch_bounds__(256) void mma_gemm_ca(
    const __nv_bfloat16* __restrict__ Ahi, const __nv_bfloat16* __restrict__ Alo,
    const __nv_bfloat16* __restrict__ Bhi, const __nv_bfloat16* __restrict__ Blo,
    float* __restrict__ C, int M, int N, int K)
{
    extern __shared__ char smem[];
    const uint32_t smem_u = smem_u32(smem);
    const int tid  = threadIdx.x;
    const int wid  = tid >> 5;
    const int lane = tid & 31;
    const int warp_m = wid & 3;             // 4 x 32 rows
    const int warp_n = wid >> 2;            // 2 x 32 cols

    const int bm = blockIdx.y * 128;
    const int bn = blockIdx.x * 64;

    const int grp = lane >> 3, tt = lane & 7;
    const int rowA = tt + (grp & 1) * 8, duA = grp >> 1;
    const int rowB = tt + (grp >> 1) * 8, duB = grp & 1;

    const __nv_bfloat16* gAhi = Ahi + (size_t)bm * K;
    const __nv_bfloat16* gAlo = Alo + (size_t)bm * K;
    const __nv_bfloat16* gBhi = Bhi + (size_t)bn * K;
    const __nv_bfloat16* gBlo = Blo + (size_t)bn * K;

    float acc[2][4][4];
#pragma unroll
    for (int i = 0; i < 2; i++)
#pragma unroll
        for (int j = 0; j < 4; j++)
#pragma unroll
            for (int r = 0; r < 4; r++) acc[i][j][r] = 0.0f;

    const int nch = K >> 6;
    gemm_stage_load(smem_u, gAhi, gAlo, gBhi, gBlo, K, 0, tid);

    for (int kc = 0; kc < nch; kc++) {
        if (kc + 1 < nch) {
            gemm_stage_load(smem_u + ((kc + 1) & 1) * GS_STAGE,
                            gAhi, gAlo, gBhi, gBlo, K, (kc + 1) << 6, tid);
            asm volatile("cp.async.wait_group 1;" ::: "memory");
        } else {
            asm volatile("cp.async.wait_group 0;" ::: "memory");
        }
        __syncthreads();

        const uint32_t st  = smem_u + (kc & 1) * GS_STAGE;
        const uint32_t stAh = st,           stAl = st + 16384;
        const uint32_t stBh = st + 32768,   stBl = st + 40960;

#pragma unroll
        for (int ks = 0; ks < 4; ks++) {
            const int u0 = ks * 2;
            uint32_t aH[2][4], aL[2][4];
#pragma unroll
            for (int mt = 0; mt < 2; mt++) {
                int row = warp_m * 32 + mt * 16 + rowA;
                uint32_t off = row * 128 + (((u0 + duA) ^ (row & 7)) << 4);
                ldsm4(aH[mt], stAh + off);
                ldsm4(aL[mt], stAl + off);
            }
            uint32_t bH[4][2], bL[4][2];
#pragma unroll
            for (int p = 0; p < 2; p++) {
                int row = warp_n * 32 + p * 16 + rowB;
                uint32_t off = row * 128 + (((u0 + duB) ^ (row & 7)) << 4);
                uint32_t rh[4], rl[4];
                ldsm4(rh, stBh + off);
                ldsm4(rl, stBl + off);
                bH[2*p][0]=rh[0]; bH[2*p][1]=rh[1]; bH[2*p+1][0]=rh[2]; bH[2*p+1][1]=rh[3];
                bL[2*p][0]=rl[0]; bL[2*p][1]=rl[1]; bL[2*p+1][0]=rl[2]; bL[2*p+1][1]=rl[3];
            }
#pragma unroll
            for (int mt = 0; mt < 2; mt++)
#pragma unroll
                for (int nt = 0; nt < 4; nt++) {
                    mma_bf16(acc[mt][nt], aH[mt], bH[nt]);
                    mma_bf16(acc[mt][nt], aH[mt], bL[nt]);
                    mma_bf16(acc[mt][nt], aL[mt], bH[nt]);
                }
        }
        __syncthreads();
    }

#pragma unroll
    for (int mt = 0; mt < 2; mt++) {
        int row = bm + warp_m * 32 + mt * 16 + (lane >> 2);
#pragma unroll
        for (int nt = 0; nt < 4; nt++) {
            int col = bn + warp_n * 32 + nt * 8 + (lane & 3) * 2;
            *(float2*)(C + (size_t)row * N + col) =
                make_float2(acc[mt][nt][0], acc[mt][nt][1]);
            *(float2*)(C + (size_t)(row + 8) * N + col) =
                make_float2(acc[mt][nt][2], acc[mt][nt][3]);
        }
    }
}

// ---------------------------------------------------------------------------
// RoPE + split: reads fp32 g_qkv, writes bf16 hi/lo q (pre-scaled), k, v.
// Threads: (tok, head 0..47, d 0..63).
// ---------------------------------------------------------------------------
__global__ __launch_bounds__(256) void rope_split_kernel(
    const float* __restrict__ qkv, const int* __restrict__ positions,
    __nv_bfloat16* __restrict__ qhi, __nv_bfloat16* __restrict__ qlo,
    __nv_bfloat16* __restrict__ khi, __nv_bfloat16* __restrict__ klo,
    __nv_bfloat16* __restrict__ vhi, __nv_bfloat16* __restrict__ vlo)
{
    int idx  = blockIdx.x * blockDim.x + threadIdx.x;
    int d    = idx & 63;
    int t    = idx >> 6;
    int head = t % 48;
    int tok  = t / 48;
    const float scale = 0.08838834764831845f;   // 1/sqrt(128)

    if (head < 40) {
        float pos = (float)positions[tok];
        float freq = pos * expf(-(float)d * 0.21586735246819178f);
        float s, c;
        sincosf(freq, &s, &c);
        const float* p = qkv + (size_t)tok * QKV_N +
                         (head < 32 ? head * 128 : 4096 + (head - 32) * 128);
        float x1 = p[d], x2 = p[d + 64];
        float r1 = x1 * c - x2 * s;
        float r2 = x2 * c + x1 * s;
        __nv_bfloat16 *dh, *dl;
        if (head < 32) {
            r1 *= scale; r2 *= scale;
            size_t o = ((size_t)tok * NHEADS + head) * HDIM;
            dh = qhi + o; dl = qlo + o;
        } else {
            size_t o = ((size_t)tok * NKV + (head - 32)) * HDIM;
            dh = khi + o; dl = klo + o;
        }
        __nv_bfloat16 h1 = __float2bfloat16(r1);
        __nv_bfloat16 h2 = __float2bfloat16(r2);
        dh[d]      = h1;  dl[d]      = __float2bfloat16(r1 - __bfloat162float(h1));
        dh[d + 64] = h2;  dl[d + 64] = __float2bfloat16(r2 - __bfloat162float(h2));
    } else {
        int gk = head - 40;
        const float* p = qkv + (size_t)tok * QKV_N + 5120 + gk * 128;
        size_t o = ((size_t)tok * NKV + gk) * HDIM;
        float x1 = p[d], x2 = p[d + 64];
        __nv_bfloat16 h1 = __float2bfloat16(x1);
        __nv_bfloat16 h2 = __float2bfloat16(x2);
        vhi[o + d]      = h1;  vlo[o + d]      = __float2bfloat16(x1 - __bfloat162float(h1));
        vhi[o + d + 64] = h2;  vlo[o + d + 64] = __float2bfloat16(x2 - __bfloat162float(h2));
    }
}

// ---------------------------------------------------------------------------
// Tensor-core causal flash attention (split bf16, fp32 softmax in registers).
// Block = (b, h, 64-row q-tile), 128 threads (4 warps); warp = 16 q-rows.
// smem: Q/K/V hi+lo, each [64][128] bf16 (256B rows, XOR-swizzled) = 96KB.
// ---------------------------------------------------------------------------
#define FL_SMEM_BYTES (6 * 16384)

__global__ __launch_bounds__(128) void flash_mma_kernel(
    const __nv_bfloat16* __restrict__ qhi, const __nv_bfloat16* __restrict__ qlo,
    const __nv_bfloat16* __restrict__ khi, const __nv_bfloat16* __restrict__ klo,
    const __nv_bfloat16* __restrict__ vhi, const __nv_bfloat16* __restrict__ vlo,
    __nv_bfloat16* __restrict__ out_hi, __nv_bfloat16* __restrict__ out_lo)
{
    extern __shared__ char sm[];
    const uint32_t sQh = smem_u32(sm);
    const uint32_t sQl = sQh + 16384;
    const uint32_t sKh = sQh + 32768;
    const uint32_t sKl = sQh + 49152;
    const uint32_t sVh = sQh + 65536;
    const uint32_t sVl = sQh + 81920;

    const int tid  = threadIdx.x;
    const int wid  = tid >> 5;
    const int lane = tid & 31;

    const int bid = blockIdx.x;
    const int qt  = bid & 31;
    const int h   = (bid >> 5) & 31;
    const int b   = bid >> 10;
    const int g   = h >> 2;

    const int grp = lane >> 3, tt = lane & 7;
    const int rowA = tt + (grp & 1) * 8, duA = grp >> 1;    // non-trans A
    const int rowB = tt + (grp >> 1) * 8, duB = grp & 1;    // non-trans B
    // trans (V): matrix grp: k-half = grp&1, n-half = grp>>1
    const int rowV = tt + (grp & 1) * 8, dnV = grp >> 1;

    // ---- load Q tile (once): 2048 x 16B over 128 threads
#pragma unroll
    for (int i = 0; i < 16; i++) {
        int lin = tid + 128 * i;
        int half = lin >> 10, rem = lin & 1023;
        int r = rem >> 4, u = rem & 15;
        size_t tok = (size_t)(b * SEQ + qt * 64 + r);
        const __nv_bfloat16* src = (half ? qlo : qhi) + (tok * NHEADS + h) * HDIM + u * 8;
        uint32_t dst = (half ? sQl : sQh) + r * 256 + ((u ^ (r & 7)) << 4);
        *(uint4*)(sm + (dst - sQh)) = *(const uint4*)src;
    }

    float m0 = -1e30f, m1 = -1e30f, l0 = 0.0f, l1 = 0.0f;
    float oacc[16][4];
#pragma unroll
    for (int i = 0; i < 16; i++)
#pragma unroll
        for (int r = 0; r < 4; r++) oacc[i][r] = 0.0f;

    __syncthreads();

    for (int jt = 0; jt <= qt; jt++) {
        __syncthreads();    // previous iteration's smem reads complete
        // ---- load K, V tiles: 4096 x 16B over 128 threads
#pragma unroll
        for (int i = 0; i < 32; i++) {
            int lin = tid + 128 * i;
            int sel = lin >> 10, rem = lin & 1023;
            int r = rem >> 4, u = rem & 15;
            size_t tok = (size_t)(b * SEQ + jt * 64 + r);
            const __nv_bfloat16* base =
                (sel == 0) ? khi : (sel == 1) ? klo : (sel == 2) ? vhi : vlo;
            uint32_t sbase =
                (sel == 0) ? sKh : (sel == 1) ? sKl : (sel == 2) ? sVh : sVl;
            const __nv_bfloat16* src = base + (tok * NKV + g) * HDIM + u * 8;
            uint32_t dst = sbase + r * 256 + ((u ^ (r & 7)) << 4);
            *(uint4*)(sm + (dst - sQh)) = *(const uint4*)src;
        }
        __syncthreads();

        // ---- S = Q K^T (warp: 16 q-rows x 64 k-cols, 8 n8-tiles)
        float sacc[8][4];
#pragma unroll
        for (int i = 0; i < 8; i++)
#pragma unroll
            for (int r = 0; r < 4; r++) sacc[i][r] = 0.0f;

#pragma unroll
        for (int ks = 0; ks < 8; ks++) {
            const int u0 = ks * 2;
            uint32_t aH[4], aL[4];
            {
                int row = wid * 16 + rowA;
                uint32_t off = row * 256 + (((u0 + duA) ^ (row & 7)) << 4);
                ldsm4(aH, sQh + off);
                ldsm4(aL, sQl + off);
            }
#pragma unroll
            for (int p = 0; p < 4; p++) {
                int row = p * 16 + rowB;
                uint32_t off = row * 256 + (((u0 + duB) ^ (row & 7)) << 4);
                uint32_t rh[4], rl[4];
                ldsm4(rh, sKh + off);
                ldsm4(rl, sKl + off);
                uint32_t bh0[2] = {rh[0], rh[1]}, bh1[2] = {rh[2], rh[3]};
                uint32_t bl0[2] = {rl[0], rl[1]}, bl1[2] = {rl[2], rl[3]};
                mma_bf16(sacc[2*p],   aH, bh0);
                mma_bf16(sacc[2*p],   aH, bl0);
                mma_bf16(sacc[2*p],   aL, bh0);
                mma_bf16(sacc[2*p+1], aH, bh1);
                mma_bf16(sacc[2*p+1], aH, bl1);
                mma_bf16(sacc[2*p+1], aL, bh1);
            }
        }

        // ---- causal mask (diag tile): local q-row vs local k-col
        if (jt == qt) {
            int qr0 = wid * 16 + (lane >> 2);
#pragma unroll
            for (int nt = 0; nt < 8; nt++) {
                int col = nt * 8 + (lane & 3) * 2;
                if (col     > qr0)     sacc[nt][0] = -1e30f;
                if (col + 1 > qr0)     sacc[nt][1] = -1e30f;
                if (col     > qr0 + 8) sacc[nt][2] = -1e30f;
                if (col + 1 > qr0 + 8) sacc[nt][3] = -1e30f;
            }
        }

        // ---- online softmax (per-thread rows r0, r0+8; reduce over lane&3)
        float mx0 = -1e30f, mx1 = -1e30f;
#pragma unroll
        for (int nt = 0; nt < 8; nt++) {
            mx0 = fmaxf(mx0, fmaxf(sacc[nt][0], sacc[nt][1]));
            mx1 = fmaxf(mx1, fmaxf(sacc[nt][2], sacc[nt][3]));
        }
        mx0 = fmaxf(mx0, __shfl_xor_sync(0xffffffffu, mx0, 1));
        mx0 = fmaxf(mx0, __shfl_xor_sync(0xffffffffu, mx0, 2));
        mx1 = fmaxf(mx1, __shfl_xor_sync(0xffffffffu, mx1, 1));
        mx1 = fmaxf(mx1, __shfl_xor_sync(0xffffffffu, mx1, 2));
        float mn0 = fmaxf(m0, mx0), mn1 = fmaxf(m1, mx1);
        float corr0 = __expf(m0 - mn0), corr1 = __expf(m1 - mn1);
        m0 = mn0; m1 = mn1;

        float sum0 = 0.0f, sum1 = 0.0f;
#pragma unroll
        for (int nt = 0; nt < 8; nt++) {
            sacc[nt][0] = __expf(sacc[nt][0] - mn0);
            sacc[nt][1] = __expf(sacc[nt][1] - mn0);
            sacc[nt][2] = __expf(sacc[nt][2] - mn1);
            sacc[nt][3] = __expf(sacc[nt][3] - mn1);
            sum0 += sacc[nt][0] + sacc[nt][1];
            sum1 += sacc[nt][2] + sacc[nt][3];
        }
        sum0 += __shfl_xor_sync(0xffffffffu, sum0, 1);
        sum0 += __shfl_xor_sync(0xffffffffu, sum0, 2);
        sum1 += __shfl_xor_sync(0xffffffffu, sum1, 1);
        sum1 += __shfl_xor_sync(0xffffffffu, sum1, 2);
        l0 = l0 * corr0 + sum0;
        l1 = l1 * corr1 + sum1;

#pragma unroll
        for (int nt = 0; nt < 16; nt++) {
            oacc[nt][0] *= corr0; oacc[nt][1] *= corr0;
            oacc[nt][2] *= corr1; oacc[nt][3] *= corr1;
        }

        // ---- O += P V  (P split hi/lo in registers, V via ldmatrix.trans)
#pragma unroll
        for (int kt = 0; kt < 4; kt++) {
            const float* sa = sacc[2*kt];
            const float* sb = sacc[2*kt+1];
            float h00 = __bfloat162float(__float2bfloat16(sa[0]));
            float h01 = __bfloat162float(__float2bfloat16(sa[1]));
            float h02 = __bfloat162float(__float2bfloat16(sa[2]));
            float h03 = __bfloat162float(__float2bfloat16(sa[3]));
            float h10 = __bfloat162float(__float2bfloat16(sb[0]));
            float h11 = __bfloat162float(__float2bfloat16(sb[1]));
            float h12 = __bfloat162float(__float2bfloat16(sb[2]));
            float h13 = __bfloat162float(__float2bfloat16(sb[3]));
            uint32_t ah[4], al[4];
            ah[0] = pack_bf16(h00, h01);            al[0] = pack_bf16(sa[0]-h00, sa[1]-h01);
            ah[1] = pack_bf16(h02, h03);            al[1] = pack_bf16(sa[2]-h02, sa[3]-h03);
            ah[2] = pack_bf16(h10, h11);            al[2] = pack_bf16(sb[0]-h10, sb[1]-h11);
            ah[3] = pack_bf16(h12, h13);            al[3] = pack_bf16(sb[2]-h12, sb[3]-h13);

#pragma unroll
            for (int nn = 0; nn < 8; nn++) {
                int row = kt * 16 + rowV;
                int u = nn * 2 + dnV;
                uint32_t off = row * 256 + (((u) ^ (row & 7)) << 4);
                uint32_t rvh[4], rvl[4];
                ldsm4t(rvh, sVh + off);
                ldsm4t(rvl, sVl + off);
                uint32_t bh0[2] = {rvh[0], rvh[1]}, bh1[2] = {rvh[2], rvh[3]};
                uint32_t bl0[2] = {rvl[0], rvl[1]}, bl1[2] = {rvl[2], rvl[3]};
                mma_bf16(oacc[2*nn],   ah, bh0);
                mma_bf16(oacc[2*nn],   ah, bl0);
                mma_bf16(oacc[2*nn],   al, bh0);
                mma_bf16(oacc[2*nn+1], ah, bh1);
                mma_bf16(oacc[2*nn+1], ah, bl1);
                mma_bf16(oacc[2*nn+1], al, bh1);
            }
        }
    }

    // ---- epilogue: normalize, split bf16 hi/lo, write
    float inv0 = 1.0f / l0, inv1 = 1.0f / l1;
    size_t row0 = (size_t)(b * SEQ + qt * 64 + wid * 16 + (lane >> 2));
    size_t row1 = row0 + 8;
#pragma unroll
    for (int nt = 0; nt < 16; nt++) {
        int col = h * 128 + nt * 8 + (lane & 3) * 2;
        float v00 = oacc[nt][0] * inv0, v01 = oacc[nt][1] * inv0;
        float v10 = oacc[nt][2] * inv1, v11 = oacc[nt][3] * inv1;
        __nv_bfloat16 a0 = __float2bfloat16(v00), a1 = __float2bfloat16(v01);
        __nv_bfloat16 b0 = __float2bfloat16(v10), b1 = __float2bfloat16(v11);
        *(__nv_bfloat162*)(out_hi + row0 * HID + col) = __nv_bfloat162(a0, a1);
        *(__nv_bfloat162*)(out_lo + row0 * HID + col) = __nv_bfloat162(
            __float2bfloat16(v00 - __bfloat162float(a0)),
            __float2bfloat16(v01 - __bfloat162float(a1)));
        *(__nv_bfloat162*)(out_hi + row1 * HID + col) = __nv_bfloat162(b0, b1);
        *(__nv_bfloat162*)(out_lo + row1 * HID + col) = __nv_bfloat162(
            __float2bfloat16(v10 - __bfloat162float(b0)),
            __float2bfloat16(v11 - __bfloat162float(b1)));
    }
}

// ---------------------------------------------------------------------------
extern "C" void kernel_launch(void* const* d_in, const int* in_sizes, int n_in,
                              void* d_out, int out_size)
{
    const float* hidden    = (const float*)d_in[0];
    const int*   positions = (const int*)  d_in[1];
    const float* w_qkv     = (const float*)d_in[2];
    const float* w_o       = (const float*)d_in[3];
    float*       out       = (float*)d_out;

    float* qkv;
    cudaGetSymbolAddress((void**)&qkv, g_qkv);
    __nv_bfloat16 *hid_hi, *hid_lo, *wqkv_hi, *wqkv_lo;
    __nv_bfloat16 *attn_hi, *attn_lo, *wo_hi, *wo_lo;
    __nv_bfloat16 *q_hi, *q_lo, *k_hi, *k_lo, *v_hi, *v_lo;
    cudaGetSymbolAddress((void**)&hid_hi,  g_hid_hi);
    cudaGetSymbolAddress((void**)&hid_lo,  g_hid_lo);
    cudaGetSymbolAddress((void**)&wqkv_hi, g_wqkv_hi);
    cudaGetSymbolAddress((void**)&wqkv_lo, g_wqkv_lo);
    cudaGetSymbolAddress((void**)&attn_hi, g_attn_hi);
    cudaGetSymbolAddress((void**)&attn_lo, g_attn_lo);
    cudaGetSymbolAddress((void**)&wo_hi,   g_wo_hi);
    cudaGetSymbolAddress((void**)&wo_lo,   g_wo_lo);
    cudaGetSymbolAddress((void**)&q_hi,    g_q_hi);
    cudaGetSymbolAddress((void**)&q_lo,    g_q_lo);
    cudaGetSymbolAddress((void**)&k_hi,    g_k_hi);
    cudaGetSymbolAddress((void**)&k_lo,    g_k_lo);
    cudaGetSymbolAddress((void**)&v_hi,    g_v_hi);
    cudaGetSymbolAddress((void**)&v_lo,    g_v_lo);

    cudaFuncSetAttribute(mma_gemm_ca,
                         cudaFuncAttributeMaxDynamicSharedMemorySize,
                         GEMM_SMEM_BYTES);
    cudaFuncSetAttribute(flash_mma_kernel,
                         cudaFuncAttributeMaxDynamicSharedMemorySize,
                         FL_SMEM_BYTES);

    // 0) split inputs to bf16 hi/lo
    {
        size_t n_hid  = (size_t)MTOK * HID;
        size_t n_wqkv = (size_t)QKV_N * HID;
        size_t n_wo   = (size_t)HID * HID;
        split_bf16_kernel<<<(unsigned)(n_hid  / 1024), 256>>>(hidden, hid_hi,  hid_lo,  n_hid);
        split_bf16_kernel<<<(unsigned)(n_wqkv / 1024), 256>>>(w_qkv,  wqkv_hi, wqkv_lo, n_wqkv);
        split_bf16_kernel<<<(unsigned)(n_wo   / 1024), 256>>>(w_o,    wo_hi,   wo_lo,   n_wo);
    }

    // 1) qkv = hidden @ w_qkv^T  (tensor cores, cp.async pipelined)
    mma_gemm_ca<<<dim3(QKV_N / 64, MTOK / 128), 256, GEMM_SMEM_BYTES>>>(
        hid_hi, hid_lo, wqkv_hi, wqkv_lo, qkv, MTOK, QKV_N, HID);

    // 2) RoPE + split q/k/v to bf16 hi/lo (q pre-scaled)
    rope_split_kernel<<<(BATCH * SEQ * 48 * 64) / 256, 256>>>(
        qkv, positions, q_hi, q_lo, k_hi, k_lo, v_hi, v_lo);

    // 3) causal GQA flash attention (tensor cores) -> attn bf16 hi/lo
    flash_mma_kernel<<<BATCH * NHEADS * (SEQ / 64), 128, FL_SMEM_BYTES>>>(
        q_hi, q_lo, k_hi, k_lo, v_hi, v_lo, attn_hi, attn_lo);

    // 4) out = attn @ w_o^T (tensor cores, cp.async pipelined)
    mma_gemm_ca<<<dim3(HID / 64, MTOK / 128), 256, GEMM_SMEM_BYTES>>>(
        attn_hi, attn_lo, wo_hi, wo_lo, out, MTOK, HID, HID);
}

// round 8
// speedup vs baseline: 3.2636x; 1.0217x over previous
#include <cuda_runtime.h>
#include <cuda_bf16.h>
#include <cstdint>

// Problem constants
#define BATCH    2
#define SEQ      2048
#define HID      4096
#define NHEADS   32
#define NKV      8
#define HDIM     128
#define QKV_N    6144          // 32*128 + 8*128 + 8*128
#define MTOK     (BATCH*SEQ)   // 4096 token rows

// ---------------------------------------------------------------------------
// Scratch (device globals: allowed; no runtime allocation)
// ---------------------------------------------------------------------------
__device__ float g_qkv[(size_t)MTOK * QKV_N];    // fp32 qkv after projection

__device__ __nv_bfloat16 g_hid_hi[(size_t)MTOK * HID];
__device__ __nv_bfloat16 g_hid_lo[(size_t)MTOK * HID];
__device__ __nv_bfloat16 g_wqkv_hi[(size_t)QKV_N * HID];
__device__ __nv_bfloat16 g_wqkv_lo[(size_t)QKV_N * HID];
__device__ __nv_bfloat16 g_attn_hi[(size_t)MTOK * HID];
__device__ __nv_bfloat16 g_attn_lo[(size_t)MTOK * HID];
__device__ __nv_bfloat16 g_wo_hi[(size_t)HID * HID];
__device__ __nv_bfloat16 g_wo_lo[(size_t)HID * HID];

// rope'd q/k and v, split bf16 hi/lo
__device__ __nv_bfloat16 g_q_hi[(size_t)MTOK * NHEADS * HDIM];
__device__ __nv_bfloat16 g_q_lo[(size_t)MTOK * NHEADS * HDIM];
__device__ __nv_bfloat16 g_k_hi[(size_t)MTOK * NKV * HDIM];
__device__ __nv_bfloat16 g_k_lo[(size_t)MTOK * NKV * HDIM];
__device__ __nv_bfloat16 g_v_hi[(size_t)MTOK * NKV * HDIM];
__device__ __nv_bfloat16 g_v_lo[(size_t)MTOK * NKV * HDIM];

// ---------------------------------------------------------------------------
// mma.sync + ldmatrix + cp.async helpers (family-agnostic on .target sm_100)
// ---------------------------------------------------------------------------
__device__ __forceinline__ uint32_t smem_u32(const void* p) {
    uint32_t a;
    asm("{ .reg .u64 t; cvta.to.shared.u64 t, %1; cvt.u32.u64 %0, t; }"
        : "=r"(a) : "l"(p));
    return a;
}
__device__ __forceinline__ void ldsm4(uint32_t* r, uint32_t addr) {
    asm volatile("ldmatrix.sync.aligned.m8n8.x4.shared.b16 {%0,%1,%2,%3}, [%4];"
        : "=r"(r[0]), "=r"(r[1]), "=r"(r[2]), "=r"(r[3]) : "r"(addr));
}
__device__ __forceinline__ void ldsm4t(uint32_t* r, uint32_t addr) {
    asm volatile("ldmatrix.sync.aligned.m8n8.x4.trans.shared.b16 {%0,%1,%2,%3}, [%4];"
        : "=r"(r[0]), "=r"(r[1]), "=r"(r[2]), "=r"(r[3]) : "r"(addr));
}
__device__ __forceinline__ void mma_bf16(float* d, const uint32_t* a, const uint32_t* b) {
    asm volatile(
        "mma.sync.aligned.m16n8k16.row.col.f32.bf16.bf16.f32 "
        "{%0,%1,%2,%3}, {%4,%5,%6,%7}, {%8,%9}, {%0,%1,%2,%3};"
        : "+f"(d[0]), "+f"(d[1]), "+f"(d[2]), "+f"(d[3])
        : "r"(a[0]), "r"(a[1]), "r"(a[2]), "r"(a[3]), "r"(b[0]), "r"(b[1]));
}
__device__ __forceinline__ void cp_async16(uint32_t s, const void* g) {
    asm volatile("cp.async.cg.shared.global [%0], [%1], 16;" :: "r"(s), "l"(g));
}
#define CP_COMMIT() asm volatile("cp.async.commit_group;" ::: "memory")

__device__ __forceinline__ uint32_t pack_bf16(float x, float y) {
    __nv_bfloat162 t = __floats2bfloat162_rn(x, y);
    return *(uint32_t*)&t;
}

// ---------------------------------------------------------------------------
// fp32 -> bf16 (hi, lo) splitter
// ---------------------------------------------------------------------------
__global__ __launch_bounds__(256) void split_bf16_kernel(
    const float* __restrict__ x,
    __nv_bfloat16* __restrict__ hi,
    __nv_bfloat16* __restrict__ lo,
    size_t n)
{
    size_t i = ((size_t)blockIdx.x * blockDim.x + threadIdx.x) * 4;
    if (i >= n) return;
    float4 v = *(const float4*)(x + i);
    float vs[4] = {v.x, v.y, v.z, v.w};
    __nv_bfloat16 h[4], l[4];
#pragma unroll
    for (int k = 0; k < 4; k++) {
        h[k] = __float2bfloat16(vs[k]);
        l[k] = __float2bfloat16(vs[k] - __bfloat162float(h[k]));
    }
    *(__nv_bfloat162*)(hi + i)     = __nv_bfloat162(h[0], h[1]);
    *(__nv_bfloat162*)(hi + i + 2) = __nv_bfloat162(h[2], h[3]);
    *(__nv_bfloat162*)(lo + i)     = __nv_bfloat162(l[0], l[1]);
    *(__nv_bfloat162*)(lo + i + 2) = __nv_bfloat162(l[2], l[3]);
}

// ---------------------------------------------------------------------------
// Tensor-core GEMM (TN), cp.async double-buffered (unchanged from round 7).
// ---------------------------------------------------------------------------
#define GS_STAGE   49152
#define GEMM_SMEM_BYTES (2 * GS_STAGE)

__device__ __forceinline__ void gemm_stage_load(
    uint32_t stu,
    const __nv_bfloat16* __restrict__ gAhi, const __nv_bfloat16* __restrict__ gAlo,
    const __nv_bfloat16* __restrict__ gBhi, const __nv_bfloat16* __restrict__ gBlo,
    int K, int ko, int tid)
{
#pragma unroll
    for (int i = 0; i < 8; i++) {           // A tiles: 2048 x 16B
        int lin = tid + 256 * i;
        int tile = lin >> 10, rem = lin & 1023;
        int r = rem >> 3, u = rem & 7;
        const __nv_bfloat16* g = (tile ? gAlo : gAhi) + (size_t)r * K + ko + u * 8;
        cp_async16(stu + tile * 16384 + r * 128 + ((u ^ (r & 7)) << 4), g);
    }
#pragma unroll
    for (int i = 0; i < 4; i++) {           // B tiles: 1024 x 16B
        int lin = tid + 256 * i;
        int tile = lin >> 9, rem = lin & 511;
        int r = rem >> 3, u = rem & 7;
        const __nv_bfloat16* g = (tile ? gBlo : gBhi) + (size_t)r * K + ko + u * 8;
        cp_async16(stu + 32768 + tile * 8192 + r * 128 + ((u ^ (r & 7)) << 4), g);
    }
    CP_COMMIT();
}

__global__ __launch_bounds__(256) void mma_gemm_ca(
    const __nv_bfloat16* __restrict__ Ahi, const __nv_bfloat16* __restrict__ Alo,
    const __nv_bfloat16* __restrict__ Bhi, const __nv_bfloat16* __restrict__ Blo,
    float* __restrict__ C, int M, int N, int K)
{
    extern __shared__ char smem[];
    const uint32_t smem_u = smem_u32(smem);
    const int tid  = threadIdx.x;
    const int wid  = tid >> 5;
    const int lane = tid & 31;
    const int warp_m = wid & 3;
    const int warp_n = wid >> 2;

    const int bm = blockIdx.y * 128;
    const int bn = blockIdx.x * 64;

    const int grp = lane >> 3, tt = lane & 7;
    const int rowA = tt + (grp & 1) * 8, duA = grp >> 1;
    const int rowB = tt + (grp >> 1) * 8, duB = grp & 1;

    const __nv_bfloat16* gAhi = Ahi + (size_t)bm * K;
    const __nv_bfloat16* gAlo = Alo + (size_t)bm * K;
    const __nv_bfloat16* gBhi = Bhi + (size_t)bn * K;
    const __nv_bfloat16* gBlo = Blo + (size_t)bn * K;

    float acc[2][4][4];
#pragma unroll
    for (int i = 0; i < 2; i++)
#pragma unroll
        for (int j = 0; j < 4; j++)
#pragma unroll
            for (int r = 0; r < 4; r++) acc[i][j][r] = 0.0f;

    const int nch = K >> 6;
    gemm_stage_load(smem_u, gAhi, gAlo, gBhi, gBlo, K, 0, tid);

    for (int kc = 0; kc < nch; kc++) {
        if (kc + 1 < nch) {
            gemm_stage_load(smem_u + ((kc + 1) & 1) * GS_STAGE,
                            gAhi, gAlo, gBhi, gBlo, K, (kc + 1) << 6, tid);
            asm volatile("cp.async.wait_group 1;" ::: "memory");
        } else {
            asm volatile("cp.async.wait_group 0;" ::: "memory");
        }
        __syncthreads();

        const uint32_t st  = smem_u + (kc & 1) * GS_STAGE;
        const uint32_t stAh = st,           stAl = st + 16384;
        const uint32_t stBh = st + 32768,   stBl = st + 40960;

#pragma unroll
        for (int ks = 0; ks < 4; ks++) {
            const int u0 = ks * 2;
            uint32_t aH[2][4], aL[2][4];
#pragma unroll
            for (int mt = 0; mt < 2; mt++) {
                int row = warp_m * 32 + mt * 16 + rowA;
                uint32_t off = row * 128 + (((u0 + duA) ^ (row & 7)) << 4);
                ldsm4(aH[mt], stAh + off);
                ldsm4(aL[mt], stAl + off);
            }
            uint32_t bH[4][2], bL[4][2];
#pragma unroll
            for (int p = 0; p < 2; p++) {
                int row = warp_n * 32 + p * 16 + rowB;
                uint32_t off = row * 128 + (((u0 + duB) ^ (row & 7)) << 4);
                uint32_t rh[4], rl[4];
                ldsm4(rh, stBh + off);
                ldsm4(rl, stBl + off);
                bH[2*p][0]=rh[0]; bH[2*p][1]=rh[1]; bH[2*p+1][0]=rh[2]; bH[2*p+1][1]=rh[3];
                bL[2*p][0]=rl[0]; bL[2*p][1]=rl[1]; bL[2*p+1][0]=rl[2]; bL[2*p+1][1]=rl[3];
            }
#pragma unroll
            for (int mt = 0; mt < 2; mt++)
#pragma unroll
                for (int nt = 0; nt < 4; nt++) {
                    mma_bf16(acc[mt][nt], aH[mt], bH[nt]);
                    mma_bf16(acc[mt][nt], aH[mt], bL[nt]);
                    mma_bf16(acc[mt][nt], aL[mt], bH[nt]);
                }
        }
        __syncthreads();
    }

#pragma unroll
    for (int mt = 0; mt < 2; mt++) {
        int row = bm + warp_m * 32 + mt * 16 + (lane >> 2);
#pragma unroll
        for (int nt = 0; nt < 4; nt++) {
            int col = bn + warp_n * 32 + nt * 8 + (lane & 3) * 2;
            *(float2*)(C + (size_t)row * N + col) =
                make_float2(acc[mt][nt][0], acc[mt][nt][1]);
            *(float2*)(C + (size_t)(row + 8) * N + col) =
                make_float2(acc[mt][nt][2], acc[mt][nt][3]);
        }
    }
}

// ---------------------------------------------------------------------------
// RoPE + split: reads fp32 g_qkv, writes bf16 hi/lo q (pre-scaled), k, v.
// ---------------------------------------------------------------------------
__global__ __launch_bounds__(256) void rope_split_kernel(
    const float* __restrict__ qkv, const int* __restrict__ positions,
    __nv_bfloat16* __restrict__ qhi, __nv_bfloat16* __restrict__ qlo,
    __nv_bfloat16* __restrict__ khi, __nv_bfloat16* __restrict__ klo,
    __nv_bfloat16* __restrict__ vhi, __nv_bfloat16* __restrict__ vlo)
{
    int idx  = blockIdx.x * blockDim.x + threadIdx.x;
    int d    = idx & 63;
    int t    = idx >> 6;
    int head = t % 48;
    int tok  = t / 48;
    const float scale = 0.08838834764831845f;   // 1/sqrt(128)

    if (head < 40) {
        float pos = (float)positions[tok];
        float freq = pos * expf(-(float)d * 0.21586735246819178f);
        float s, c;
        sincosf(freq, &s, &c);
        const float* p = qkv + (size_t)tok * QKV_N +
                         (head < 32 ? head * 128 : 4096 + (head - 32) * 128);
        float x1 = p[d], x2 = p[d + 64];
        float r1 = x1 * c - x2 * s;
        float r2 = x2 * c + x1 * s;
        __nv_bfloat16 *dh, *dl;
        if (head < 32) {
            r1 *= scale; r2 *= scale;
            size_t o = ((size_t)tok * NHEADS + head) * HDIM;
            dh = qhi + o; dl = qlo + o;
        } else {
            size_t o = ((size_t)tok * NKV + (head - 32)) * HDIM;
            dh = khi + o; dl = klo + o;
        }
        __nv_bfloat16 h1 = __float2bfloat16(r1);
        __nv_bfloat16 h2 = __float2bfloat16(r2);
        dh[d]      = h1;  dl[d]      = __float2bfloat16(r1 - __bfloat162float(h1));
        dh[d + 64] = h2;  dl[d + 64] = __float2bfloat16(r2 - __bfloat162float(h2));
    } else {
        int gk = head - 40;
        const float* p = qkv + (size_t)tok * QKV_N + 5120 + gk * 128;
        size_t o = ((size_t)tok * NKV + gk) * HDIM;
        float x1 = p[d], x2 = p[d + 64];
        __nv_bfloat16 h1 = __float2bfloat16(x1);
        __nv_bfloat16 h2 = __float2bfloat16(x2);
        vhi[o + d]      = h1;  vlo[o + d]      = __float2bfloat16(x1 - __bfloat162float(h1));
        vhi[o + d + 64] = h2;  vlo[o + d + 64] = __float2bfloat16(x2 - __bfloat162float(h2));
    }
}

// ---------------------------------------------------------------------------
// Tensor-core causal flash attention v2.
// Block = (b, h, 128-row q-tile), 256 threads (8 warps); warp = 16 q-rows.
// K/V tiles of 64 rows, cp.async double-buffered.
// smem: Q hi/lo [128][128] (64KB) + 2 stages x (K+V hi/lo, 64KB) = 192KB.
// ---------------------------------------------------------------------------
#define FL_STAGE      65536
#define FL_SMEM_BYTES (65536 + 2 * FL_STAGE)

__device__ __forceinline__ void fl_kv_load(
    char* smbase, uint32_t st_off,
    const __nv_bfloat16* __restrict__ khi, const __nv_bfloat16* __restrict__ klo,
    const __nv_bfloat16* __restrict__ vhi, const __nv_bfloat16* __restrict__ vlo,
    int b, int g, int jt, int tid, uint32_t smem_base_u)
{
#pragma unroll
    for (int i = 0; i < 16; i++) {
        int lin = tid + 256 * i;          // 0..4095 16B units
        int sel = lin >> 10, rem = lin & 1023;
        int r = rem >> 4, u = rem & 15;
        const __nv_bfloat16* base =
            (sel == 0) ? khi : (sel == 1) ? klo : (sel == 2) ? vhi : vlo;
        const __nv_bfloat16* src =
            base + ((size_t)(b * SEQ + jt * 64 + r) * NKV + g) * HDIM + u * 8;
        uint32_t dst = smem_base_u + st_off + sel * 16384 + r * 256 + ((u ^ (r & 7)) << 4);
        cp_async16(dst, src);
    }
    CP_COMMIT();
}

__global__ __launch_bounds__(256) void flash_mma2_kernel(
    const __nv_bfloat16* __restrict__ qhi, const __nv_bfloat16* __restrict__ qlo,
    const __nv_bfloat16* __restrict__ khi, const __nv_bfloat16* __restrict__ klo,
    const __nv_bfloat16* __restrict__ vhi, const __nv_bfloat16* __restrict__ vlo,
    __nv_bfloat16* __restrict__ out_hi, __nv_bfloat16* __restrict__ out_lo)
{
    extern __shared__ char sm[];
    const uint32_t smu = smem_u32(sm);
    const uint32_t sQh = smu;
    const uint32_t sQl = smu + 32768;

    const int tid  = threadIdx.x;
    const int wid  = tid >> 5;
    const int lane = tid & 31;

    const int qt = blockIdx.x & 15;           // 16 q-tiles of 128 rows
    const int h  = (blockIdx.x >> 4) & 31;
    const int b  = blockIdx.x >> 9;
    const int g  = h >> 2;

    const int grp = lane >> 3, tt = lane & 7;
    const int rowA = tt + (grp & 1) * 8, duA = grp >> 1;
    const int rowB = tt + (grp >> 1) * 8, duB = grp & 1;
    const int rowV = tt + (grp & 1) * 8, dnV = grp >> 1;

    // ---- load Q tile (once): 4096 x 16B over 256 threads
#pragma unroll
    for (int i = 0; i < 16; i++) {
        int lin = tid + 256 * i;
        int half = lin >> 11, rem = lin & 2047;
        int r = rem >> 4, u = rem & 15;
        const __nv_bfloat16* src = (half ? qlo : qhi) +
            ((size_t)(b * SEQ + qt * 128 + r) * NHEADS + h) * HDIM + u * 8;
        uint32_t doff = (half ? 32768 : 0) + r * 256 + ((u ^ (r & 7)) << 4);
        *(uint4*)(sm + doff) = *(const uint4*)src;
    }

    float m0 = -1e30f, m1 = -1e30f, l0 = 0.0f, l1 = 0.0f;
    float oacc[16][4];
#pragma unroll
    for (int i = 0; i < 16; i++)
#pragma unroll
        for (int r = 0; r < 4; r++) oacc[i][r] = 0.0f;

    const int njt = 2 * qt + 2;
    fl_kv_load(sm, 65536, khi, klo, vhi, vlo, b, g, 0, tid, smu);

    for (int jt = 0; jt < njt; jt++) {
        if (jt + 1 < njt) {
            fl_kv_load(sm, 65536 + ((jt + 1) & 1) * FL_STAGE,
                       khi, klo, vhi, vlo, b, g, jt + 1, tid, smu);
            asm volatile("cp.async.wait_group 1;" ::: "memory");
        } else {
            asm volatile("cp.async.wait_group 0;" ::: "memory");
        }
        __syncthreads();

        const uint32_t st  = smu + 65536 + (jt & 1) * FL_STAGE;
        const uint32_t sKh = st,           sKl = st + 16384;
        const uint32_t sVh = st + 32768,   sVl = st + 49152;

        // ---- S = Q K^T (warp: 16 q-rows x 64 k-cols)
        float sacc[8][4];
#pragma unroll
        for (int i = 0; i < 8; i++)
#pragma unroll
            for (int r = 0; r < 4; r++) sacc[i][r] = 0.0f;

#pragma unroll
        for (int ks = 0; ks < 8; ks++) {
            const int u0 = ks * 2;
            uint32_t aH[4], aL[4];
            {
                int row = wid * 16 + rowA;
                uint32_t off = row * 256 + (((u0 + duA) ^ (row & 7)) << 4);
                ldsm4(aH, sQh + off);
                ldsm4(aL, sQl + off);
            }
#pragma unroll
            for (int p = 0; p < 4; p++) {
                int row = p * 16 + rowB;
                uint32_t off = row * 256 + (((u0 + duB) ^ (row & 7)) << 4);
                uint32_t rh[4], rl[4];
                ldsm4(rh, sKh + off);
                ldsm4(rl, sKl + off);
                uint32_t bh0[2] = {rh[0], rh[1]}, bh1[2] = {rh[2], rh[3]};
                uint32_t bl0[2] = {rl[0], rl[1]}, bl1[2] = {rl[2], rl[3]};
                mma_bf16(sacc[2*p],   aH, bh0);
                mma_bf16(sacc[2*p],   aH, bl0);
                mma_bf16(sacc[2*p],   aL, bh0);
                mma_bf16(sacc[2*p+1], aH, bh1);
                mma_bf16(sacc[2*p+1], aH, bl1);
                mma_bf16(sacc[2*p+1], aL, bh1);
            }
        }

        // ---- causal mask (global indices; only tiles crossing the diagonal)
        {
            int rmin = qt * 128 + wid * 16;
            if (jt * 64 + 63 > rmin) {
                int r0 = rmin + (lane >> 2);
#pragma unroll
                for (int nt = 0; nt < 8; nt++) {
                    int col = jt * 64 + nt * 8 + (lane & 3) * 2;
                    if (col     > r0)     sacc[nt][0] = -1e30f;
                    if (col + 1 > r0)     sacc[nt][1] = -1e30f;
                    if (col     > r0 + 8) sacc[nt][2] = -1e30f;
                    if (col + 1 > r0 + 8) sacc[nt][3] = -1e30f;
                }
            }
        }

        // ---- online softmax (rows r0, r0+8; reduce over lane&3 group)
        float mx0 = -1e30f, mx1 = -1e30f;
#pragma unroll
        for (int nt = 0; nt < 8; nt++) {
            mx0 = fmaxf(mx0, fmaxf(sacc[nt][0], sacc[nt][1]));
            mx1 = fmaxf(mx1, fmaxf(sacc[nt][2], sacc[nt][3]));
        }
        mx0 = fmaxf(mx0, __shfl_xor_sync(0xffffffffu, mx0, 1));
        mx0 = fmaxf(mx0, __shfl_xor_sync(0xffffffffu, mx0, 2));
        mx1 = fmaxf(mx1, __shfl_xor_sync(0xffffffffu, mx1, 1));
        mx1 = fmaxf(mx1, __shfl_xor_sync(0xffffffffu, mx1, 2));
        float mn0 = fmaxf(m0, mx0), mn1 = fmaxf(m1, mx1);
        float corr0 = __expf(m0 - mn0), corr1 = __expf(m1 - mn1);
        m0 = mn0; m1 = mn1;

        float sum0 = 0.0f, sum1 = 0.0f;
#pragma unroll
        for (int nt = 0; nt < 8; nt++) {
            sacc[nt][0] = __expf(sacc[nt][0] - mn0);
            sacc[nt][1] = __expf(sacc[nt][1] - mn0);
            sacc[nt][2] = __expf(sacc[nt][2] - mn1);
            sacc[nt][3] = __expf(sacc[nt][3] - mn1);
            sum0 += sacc[nt][0] + sacc[nt][1];
            sum1 += sacc[nt][2] + sacc[nt][3];
        }
        sum0 += __shfl_xor_sync(0xffffffffu, sum0, 1);
        sum0 += __shfl_xor_sync(0xffffffffu, sum0, 2);
        sum1 += __shfl_xor_sync(0xffffffffu, sum1, 1);
        sum1 += __shfl_xor_sync(0xffffffffu, sum1, 2);
        l0 = l0 * corr0 + sum0;
        l1 = l1 * corr1 + sum1;

#pragma unroll
        for (int nt = 0; nt < 16; nt++) {
            oacc[nt][0] *= corr0; oacc[nt][1] *= corr0;
            oacc[nt][2] *= corr1; oacc[nt][3] *= corr1;
        }

        // ---- O += P V (P split hi/lo in registers, V via ldmatrix.trans)
#pragma unroll
        for (int kt = 0; kt < 4; kt++) {
            const float* sa = sacc[2*kt];
            const float* sb = sacc[2*kt+1];
            float h00 = __bfloat162float(__float2bfloat16(sa[0]));
            float h01 = __bfloat162float(__float2bfloat16(sa[1]));
            float h02 = __bfloat162float(__float2bfloat16(sa[2]));
            float h03 = __bfloat162float(__float2bfloat16(sa[3]));
            float h10 = __bfloat162float(__float2bfloat16(sb[0]));
            float h11 = __bfloat162float(__float2bfloat16(sb[1]));
            float h12 = __bfloat162float(__float2bfloat16(sb[2]));
            float h13 = __bfloat162float(__float2bfloat16(sb[3]));
            uint32_t ah[4], al[4];
            ah[0] = pack_bf16(h00, h01);  al[0] = pack_bf16(sa[0]-h00, sa[1]-h01);
            ah[1] = pack_bf16(h02, h03);  al[1] = pack_bf16(sa[2]-h02, sa[3]-h03);
            ah[2] = pack_bf16(h10, h11);  al[2] = pack_bf16(sb[0]-h10, sb[1]-h11);
            ah[3] = pack_bf16(h12, h13);  al[3] = pack_bf16(sb[2]-h12, sb[3]-h13);

#pragma unroll
            for (int nn = 0; nn < 8; nn++) {
                int row = kt * 16 + rowV;
                int u = nn * 2 + dnV;
                uint32_t off = row * 256 + ((u ^ (row & 7)) << 4);
                uint32_t rvh[4], rvl[4];
                ldsm4t(rvh, sVh + off);
                ldsm4t(rvl, sVl + off);
                uint32_t bh0[2] = {rvh[0], rvh[1]}, bh1[2] = {rvh[2], rvh[3]};
                uint32_t bl0[2] = {rvl[0], rvl[1]}, bl1[2] = {rvl[2], rvl[3]};
                mma_bf16(oacc[2*nn],   ah, bh0);
                mma_bf16(oacc[2*nn],   ah, bl0);
                mma_bf16(oacc[2*nn],   al, bh0);
                mma_bf16(oacc[2*nn+1], ah, bh1);
                mma_bf16(oacc[2*nn+1], ah, bl1);
                mma_bf16(oacc[2*nn+1], al, bh1);
            }
        }
        __syncthreads();
    }

    // ---- epilogue: normalize, split bf16 hi/lo, write
    float inv0 = 1.0f / l0, inv1 = 1.0f / l1;
    size_t row0 = (size_t)(b * SEQ + qt * 128 + wid * 16 + (lane >> 2));
    size_t row1 = row0 + 8;
#pragma unroll
    for (int nt = 0; nt < 16; nt++) {
        int col = h * 128 + nt * 8 + (lane & 3) * 2;
        float v00 = oacc[nt][0] * inv0, v01 = oacc[nt][1] * inv0;
        float v10 = oacc[nt][2] * inv1, v11 = oacc[nt][3] * inv1;
        __nv_bfloat16 a0 = __float2bfloat16(v00), a1 = __float2bfloat16(v01);
        __nv_bfloat16 b0 = __float2bfloat16(v10), b1 = __float2bfloat16(v11);
        *(__nv_bfloat162*)(out_hi + row0 * HID + col) = __nv_bfloat162(a0, a1);
        *(__nv_bfloat162*)(out_lo + row0 * HID + col) = __nv_bfloat162(
            __float2bfloat16(v00 - __bfloat162float(a0)),
            __float2bfloat16(v01 - __bfloat162float(a1)));
        *(__nv_bfloat162*)(out_hi + row1 * HID + col) = __nv_bfloat162(b0, b1);
        *(__nv_bfloat162*)(out_lo + row1 * HID + col) = __nv_bfloat162(
            __float2bfloat16(v10 - __bfloat162float(b0)),
            __float2bfloat16(v11 - __bfloat162float(b1)));
    }
}

// ---------------------------------------------------------------------------
extern "C" void kernel_launch(void* const* d_in, const int* in_sizes, int n_in,
                              void* d_out, int out_size)
{
    const float* hidden    = (const float*)d_in[0];
    const int*   positions = (const int*)  d_in[1];
    const float* w_qkv     = (const float*)d_in[2];
    const float* w_o       = (const float*)d_in[3];
    float*       out       = (float*)d_out;

    float* qkv;
    cudaGetSymbolAddress((void**)&qkv, g_qkv);
    __nv_bfloat16 *hid_hi, *hid_lo, *wqkv_hi, *wqkv_lo;
    __nv_bfloat16 *attn_hi, *attn_lo, *wo_hi, *wo_lo;
    __nv_bfloat16 *q_hi, *q_lo, *k_hi, *k_lo, *v_hi, *v_lo;
    cudaGetSymbolAddress((void**)&hid_hi,  g_hid_hi);
    cudaGetSymbolAddress((void**)&hid_lo,  g_hid_lo);
    cudaGetSymbolAddress((void**)&wqkv_hi, g_wqkv_hi);
    cudaGetSymbolAddress((void**)&wqkv_lo, g_wqkv_lo);
    cudaGetSymbolAddress((void**)&attn_hi, g_attn_hi);
    cudaGetSymbolAddress((void**)&attn_lo, g_attn_lo);
    cudaGetSymbolAddress((void**)&wo_hi,   g_wo_hi);
    cudaGetSymbolAddress((void**)&wo_lo,   g_wo_lo);
    cudaGetSymbolAddress((void**)&q_hi,    g_q_hi);
    cudaGetSymbolAddress((void**)&q_lo,    g_q_lo);
    cudaGetSymbolAddress((void**)&k_hi,    g_k_hi);
    cudaGetSymbolAddress((void**)&k_lo,    g_k_lo);
    cudaGetSymbolAddress((void**)&v_hi,    g_v_hi);
    cudaGetSymbolAddress((void**)&v_lo,    g_v_lo);

    cudaFuncSetAttribute(mma_gemm_ca,
                         cudaFuncAttributeMaxDynamicSharedMemorySize,
                         GEMM_SMEM_BYTES);
    cudaFuncSetAttribute(flash_mma2_kernel,
                         cudaFuncAttributeMaxDynamicSharedMemorySize,
                         FL_SMEM_BYTES);

    // 0) split inputs to bf16 hi/lo
    {
        size_t n_hid  = (size_t)MTOK * HID;
        size_t n_wqkv = (size_t)QKV_N * HID;
        size_t n_wo   = (size_t)HID * HID;
        split_bf16_kernel<<<(unsigned)(n_hid  / 1024), 256>>>(hidden, hid_hi,  hid_lo,  n_hid);
        split_bf16_kernel<<<(unsigned)(n_wqkv / 1024), 256>>>(w_qkv,  wqkv_hi, wqkv_lo, n_wqkv);
        split_bf16_kernel<<<(unsigned)(n_wo   / 1024), 256>>>(w_o,    wo_hi,   wo_lo,   n_wo);
    }

    // 1) qkv = hidden @ w_qkv^T  (tensor cores, cp.async pipelined)
    mma_gemm_ca<<<dim3(QKV_N / 64, MTOK / 128), 256, GEMM_SMEM_BYTES>>>(
        hid_hi, hid_lo, wqkv_hi, wqkv_lo, qkv, MTOK, QKV_N, HID);

    // 2) RoPE + split q/k/v to bf16 hi/lo (q pre-scaled)
    rope_split_kernel<<<(BATCH * SEQ * 48 * 64) / 256, 256>>>(
        qkv, positions, q_hi, q_lo, k_hi, k_lo, v_hi, v_lo);

    // 3) causal GQA flash attention v2 (128-row q-tiles, cp.async KV pipeline)
    flash_mma2_kernel<<<BATCH * NHEADS * (SEQ / 128), 256, FL_SMEM_BYTES>>>(
        q_hi, q_lo, k_hi, k_lo, v_hi, v_lo, attn_hi, attn_lo);

    // 4) out = attn @ w_o^T (tensor cores, cp.async pipelined)
    mma_gemm_ca<<<dim3(HID / 64, MTOK / 128), 256, GEMM_SMEM_BYTES>>>(
        attn_hi, attn_lo, wo_hi, wo_lo, out, MTOK, HID, HID);
}